// round 1
// baseline (speedup 1.0000x reference)
#include <cuda_runtime.h>

// BAHDANAUplus — group recommendation scoring head.
// One warp per sample, lane = embedding dim (EMB == 32 == warp size).
//
// Inputs (metadata order):
//  0 group_inputs  int32  [B]
//  1 item_inputs   int32  [B]
//  2 members       int32  [NUM_GROUPS, 3]
//  3 user_emb      f32    [NUM_USERS, 32]
//  4 item_emb      f32    [NUM_ITEMS, 14]
//  5 genres        f32    [NUM_ITEMS, 18]
//  6 attn_W        f32    [128, 3]
//  7 attn_b        f32    [3]
//  8 pred_W1       f32    [96, 8]
//  9 pred_b1       f32    [8]
// 10 pred_W2       f32    [8, 1]
// 11 pred_b2       f32    [1]
// out: f32 [B]

#define EMB 32

__global__ __launch_bounds__(256) void bahdanau_kernel(
    const int*   __restrict__ group_inputs,
    const int*   __restrict__ item_inputs,
    const int*   __restrict__ members,
    const float* __restrict__ user_emb,
    const float* __restrict__ item_emb,
    const float* __restrict__ genres,
    const float* __restrict__ attn_W,
    const float* __restrict__ attn_b,
    const float* __restrict__ pred_W1,
    const float* __restrict__ pred_b1,
    const float* __restrict__ pred_W2,
    const float* __restrict__ pred_b2,
    float*       __restrict__ out,
    int n)
{
    // Weights staged in shared once per block.
    __shared__ float sAW[128 * 3];   // attn_W row-major [128][3]
    __shared__ float sW1t[8 * 96];   // pred_W1 transposed: sW1t[j*96 + d] = W1[d][j]
    __shared__ float sAb[3];
    __shared__ float sB1[8];
    __shared__ float sW2[8];
    __shared__ float sB2;

    const int tid = threadIdx.x;
    for (int i = tid; i < 128 * 3; i += 256) sAW[i] = attn_W[i];
    for (int i = tid; i < 96 * 8;  i += 256) {
        int d = i >> 3, j = i & 7;
        sW1t[j * 96 + d] = pred_W1[i];
    }
    if (tid < 3) sAb[tid] = attn_b[tid];
    if (tid < 8) sB1[tid] = pred_b1[tid];
    if (tid < 8) sW2[tid] = pred_W2[tid];
    if (tid == 0) sB2 = pred_b2[0];
    __syncthreads();

    const int lane = tid & 31;
    const int wid  = tid >> 5;
    const int gw   = blockIdx.x * 8 + wid;   // global warp id
    const int nw   = gridDim.x * 8;          // total warps

    // Per-lane attention-weight registers (hoisted out of the sample loop;
    // they depend only on `lane`).
    const float aw00 = sAW[(      lane) * 3 + 0], aw01 = sAW[(      lane) * 3 + 1], aw02 = sAW[(      lane) * 3 + 2];
    const float aw10 = sAW[( 32 + lane) * 3 + 0], aw11 = sAW[( 32 + lane) * 3 + 1], aw12 = sAW[( 32 + lane) * 3 + 2];
    const float aw20 = sAW[( 64 + lane) * 3 + 0], aw21 = sAW[( 64 + lane) * 3 + 1], aw22 = sAW[( 64 + lane) * 3 + 2];
    const float aw30 = sAW[( 96 + lane) * 3 + 0], aw31 = sAW[( 96 + lane) * 3 + 1], aw32 = sAW[( 96 + lane) * 3 + 2];

    for (int s = gw; s < n; s += nw) {
        const int grp = group_inputs[s];
        const int it  = item_inputs[s];

        const int m0 = members[3 * grp + 0];
        const int m1 = members[3 * grp + 1];
        const int m2 = members[3 * grp + 2];

        // Each warp reads one 128B line per member row: fully coalesced.
        const float e0 = user_emb[m0 * EMB + lane];
        const float e1 = user_emb[m1 * EMB + lane];
        const float e2 = user_emb[m2 * EMB + lane];
        // Item features: 14-d latent concat 18-d genres.
        const float itv = (lane < 14) ? item_emb[it * 14 + lane]
                                      : genres[it * 18 + (lane - 14)];

        // Attention logits: gi @ attn_W + attn_b, gi = [e0 | e1 | e2 | itv] (128-d).
        float a0 = e0 * aw00 + e1 * aw10 + e2 * aw20 + itv * aw30;
        float a1 = e0 * aw01 + e1 * aw11 + e2 * aw21 + itv * aw31;
        float a2 = e0 * aw02 + e1 * aw12 + e2 * aw22 + itv * aw32;
        #pragma unroll
        for (int off = 16; off > 0; off >>= 1) {
            a0 += __shfl_xor_sync(0xffffffffu, a0, off);
            a1 += __shfl_xor_sync(0xffffffffu, a1, off);
            a2 += __shfl_xor_sync(0xffffffffu, a2, off);
        }
        a0 += sAb[0]; a1 += sAb[1]; a2 += sAb[2];

        // Weighted member sum (raw logits, per reference).
        const float gv = a0 * e0 + a1 * e1 + a2 * e2;

        // new = [g * it_e | g | it_e] (96-d); this lane holds dims
        // {lane, 32+lane, 64+lane}.
        const float n0 = gv * itv;
        const float n1 = gv;
        const float n2 = itv;

        float h[8];
        #pragma unroll
        for (int j = 0; j < 8; j++) {
            h[j] = n0 * sW1t[j * 96 + lane]
                 + n1 * sW1t[j * 96 + 32 + lane]
                 + n2 * sW1t[j * 96 + 64 + lane];
        }
        #pragma unroll
        for (int off = 16; off > 0; off >>= 1) {
            #pragma unroll
            for (int j = 0; j < 8; j++)
                h[j] += __shfl_xor_sync(0xffffffffu, h[j], off);
        }

        float acc = sB2;
        #pragma unroll
        for (int j = 0; j < 8; j++)
            acc += fmaxf(h[j] + sB1[j], 0.0f) * sW2[j];

        const float y = 1.0f / (1.0f + expf(-acc));
        if (lane == 0) out[s] = y;
    }
}

extern "C" void kernel_launch(void* const* d_in, const int* in_sizes, int n_in,
                              void* d_out, int out_size)
{
    (void)n_in;
    const int*   group_inputs = (const int*)  d_in[0];
    const int*   item_inputs  = (const int*)  d_in[1];
    const int*   members      = (const int*)  d_in[2];
    const float* user_emb     = (const float*)d_in[3];
    const float* item_emb     = (const float*)d_in[4];
    const float* genres       = (const float*)d_in[5];
    const float* attn_W       = (const float*)d_in[6];
    const float* attn_b       = (const float*)d_in[7];
    const float* pred_W1      = (const float*)d_in[8];
    const float* pred_b1      = (const float*)d_in[9];
    const float* pred_W2      = (const float*)d_in[10];
    const float* pred_b2      = (const float*)d_in[11];
    float* out = (float*)d_out;
    const int n = in_sizes[0];
    (void)out_size;

    const int blocks = 2048;   // 8 warps/block -> 16384 warps, 8 samples/warp
    bahdanau_kernel<<<blocks, 256>>>(group_inputs, item_inputs, members,
                                     user_emb, item_emb, genres,
                                     attn_W, attn_b, pred_W1, pred_b1,
                                     pred_W2, pred_b2, out, n);
}

// round 2
// speedup vs baseline: 1.3709x; 1.3709x over previous
#include <cuda_runtime.h>

// BAHDANAUplus — group recommendation scoring head. One warp per sample.
// R2: all weights hoisted to lane-indexed registers (no shared mem, no LDS),
//     value-splitting butterfly reductions (21 shfl/sample vs 55),
//     software-pipelined index prefetch.

#define EMB 32
#define FULLMASK 0xffffffffu

__global__ __launch_bounds__(256) void bahdanau_kernel(
    const int*   __restrict__ group_inputs,
    const int*   __restrict__ item_inputs,
    const int*   __restrict__ members,
    const float* __restrict__ user_emb,
    const float* __restrict__ item_emb,
    const float* __restrict__ genres,
    const float* __restrict__ attn_W,
    const float* __restrict__ attn_b,
    const float* __restrict__ pred_W1,
    const float* __restrict__ pred_b1,
    const float* __restrict__ pred_W2,
    const float* __restrict__ pred_b2,
    float*       __restrict__ out,
    int n)
{
    const int lane = threadIdx.x & 31;
    const int wid  = threadIdx.x >> 5;
    const int gw   = blockIdx.x * 8 + wid;
    const int nw   = gridDim.x * 8;

    // ---- hoisted per-lane weights (loop invariant, lane-indexed) ----
    // attn_W is [128][3] row-major; this lane's 4 rows (one per gi segment).
    float aw[4][3];
    #pragma unroll
    for (int r = 0; r < 4; r++)
        #pragma unroll
        for (int k = 0; k < 3; k++)
            aw[r][k] = attn_W[(r * 32 + lane) * 3 + k];

    // pred_W1 is [96][8]; lane needs rows {lane, 32+lane, 64+lane}, all 8 cols.
    float w1a[8], w1b[8], w1c[8];
    #pragma unroll
    for (int j = 0; j < 8; j++) {
        w1a[j] = pred_W1[(lane)      * 8 + j];
        w1b[j] = pred_W1[(32 + lane) * 8 + j];
        w1c[j] = pred_W1[(64 + lane) * 8 + j];
    }

    // Distributed-reduction index assignments.
    const int  ja  = (lane >> 3) & 3;               // attn value owned after split
    const float abj = (ja < 3) ? attn_b[ja] : 0.0f;
    const int  jm  = (lane >> 2) & 7;               // MLP hidden unit owned
    const float b1j = pred_b1[jm];
    const float w2j = pred_W2[jm];
    const float b2  = pred_b2[0];

    const bool hi4 = (lane & 16) != 0;
    const bool hi3 = (lane & 8)  != 0;
    const bool hi2 = (lane & 4)  != 0;

    int s = gw;
    if (s >= n) return;

    // Prologue: indices for the first sample.
    int grp = group_inputs[s];
    int it  = item_inputs[s];
    int m0  = members[3 * grp + 0];
    int m1  = members[3 * grp + 1];
    int m2  = members[3 * grp + 2];

    for (;;) {
        // Issue this sample's gathers (coalesced: 1 line per row per warp).
        const float e0  = user_emb[m0 * EMB + lane];
        const float e1  = user_emb[m1 * EMB + lane];
        const float e2  = user_emb[m2 * EMB + lane];
        const float itv = (lane < 14) ? item_emb[it * 14 + lane]
                                      : genres[it * 18 + (lane - 14)];

        // Prefetch next sample's index chain while gathers are in flight.
        const int s2 = s + nw;
        const bool more = (s2 < n);
        int grp2 = 0, it2 = 0, m0n = 0, m1n = 0, m2n = 0;
        if (more) {
            grp2 = group_inputs[s2];
            it2  = item_inputs[s2];
            m0n  = members[3 * grp2 + 0];
            m1n  = members[3 * grp2 + 1];
            m2n  = members[3 * grp2 + 2];
        }

        // ---- attention logits: gi @ attn_W (+ bias later, distributed) ----
        float v0 = e0 * aw[0][0] + e1 * aw[1][0] + e2 * aw[2][0] + itv * aw[3][0];
        float v1 = e0 * aw[0][1] + e1 * aw[1][1] + e2 * aw[2][1] + itv * aw[3][1];
        float v2 = e0 * aw[0][2] + e1 * aw[1][2] + e2 * aw[2][2] + itv * aw[3][2];

        // Value-splitting reduce of {v0,v1,v2,0} over 32 lanes.
        // Stage off=16 (4 vals -> 2): keep low pair if bit4 clear.
        float s0 = hi4 ? v0 : v2;                 // send the half we don't keep
        float s1 = hi4 ? v1 : 0.0f;
        float r0 = __shfl_xor_sync(FULLMASK, s0, 16);
        float r1 = __shfl_xor_sync(FULLMASK, s1, 16);
        float u0 = (hi4 ? v2   : v0) + r0;
        float u1 = (hi4 ? 0.0f : v1) + r1;
        // Stage off=8 (2 -> 1): keep u0 if bit3 clear.
        float sx = hi3 ? u0 : u1;
        float rx = __shfl_xor_sync(FULLMASK, sx, 8);
        float av = (hi3 ? u1 : u0) + rx;          // index ja = 2*b4 + b3
        // Finish remaining lane bits 2,1,0.
        av += __shfl_xor_sync(FULLMASK, av, 4);
        av += __shfl_xor_sync(FULLMASK, av, 2);
        av += __shfl_xor_sync(FULLMASK, av, 1);
        av += abj;                                 // bias on owning lanes
        // Broadcast a0,a1,a2 to all lanes (owners: lanes 0,8,16).
        const float a0 = __shfl_sync(FULLMASK, av, 0);
        const float a1 = __shfl_sync(FULLMASK, av, 8);
        const float a2 = __shfl_sync(FULLMASK, av, 16);

        // Weighted member sum (raw logits per reference).
        const float gv = a0 * e0 + a1 * e1 + a2 * e2;

        // new = [g*it | g | it]; lane holds dims {lane, 32+lane, 64+lane}.
        const float n0 = gv * itv;

        float h[8];
        #pragma unroll
        for (int j = 0; j < 8; j++)
            h[j] = n0 * w1a[j] + gv * w1b[j] + itv * w1c[j];

        // Value-splitting reduce of 8 values over 32 lanes.
        float t[4];
        #pragma unroll
        for (int k = 0; k < 4; k++) {            // off=16: 8 -> 4 (b4 => +4)
            float snd = hi4 ? h[k] : h[k + 4];
            float rcv = __shfl_xor_sync(FULLMASK, snd, 16);
            t[k] = (hi4 ? h[k + 4] : h[k]) + rcv;
        }
        float u[2];
        #pragma unroll
        for (int k = 0; k < 2; k++) {            // off=8: 4 -> 2 (b3 => +2)
            float snd = hi3 ? t[k] : t[k + 2];
            float rcv = __shfl_xor_sync(FULLMASK, snd, 8);
            u[k] = (hi3 ? t[k + 2] : t[k]) + rcv;
        }
        {                                         // off=4: 2 -> 1 (b2 => +1)
            float snd = hi2 ? u[0] : u[1];
            float rcv = __shfl_xor_sync(FULLMASK, snd, 4);
            u[0] = (hi2 ? u[1] : u[0]) + rcv;
        }
        float hh = u[0];
        hh += __shfl_xor_sync(FULLMASK, hh, 2);   // finish bits 1,0
        hh += __shfl_xor_sync(FULLMASK, hh, 1);
        // hh = complete h_jm, jm = (lane>>2)&7.

        float p = fmaxf(hh + b1j, 0.0f) * w2j;
        // Sum the 8 distinct hidden units: orbit over lane bits 2,3,4.
        p += __shfl_xor_sync(FULLMASK, p, 4);
        p += __shfl_xor_sync(FULLMASK, p, 8);
        p += __shfl_xor_sync(FULLMASK, p, 16);

        const float acc = p + b2;
        const float y = 1.0f / (1.0f + __expf(-acc));
        if (lane == 0) out[s] = y;

        if (!more) break;
        s = s2; it = it2; m0 = m0n; m1 = m1n; m2 = m2n;
    }
}

extern "C" void kernel_launch(void* const* d_in, const int* in_sizes, int n_in,
                              void* d_out, int out_size)
{
    (void)n_in; (void)out_size;
    const int*   group_inputs = (const int*)  d_in[0];
    const int*   item_inputs  = (const int*)  d_in[1];
    const int*   members      = (const int*)  d_in[2];
    const float* user_emb     = (const float*)d_in[3];
    const float* item_emb     = (const float*)d_in[4];
    const float* genres       = (const float*)d_in[5];
    const float* attn_W       = (const float*)d_in[6];
    const float* attn_b       = (const float*)d_in[7];
    const float* pred_W1      = (const float*)d_in[8];
    const float* pred_b1      = (const float*)d_in[9];
    const float* pred_W2      = (const float*)d_in[10];
    const float* pred_b2      = (const float*)d_in[11];
    float* out = (float*)d_out;
    const int n = in_sizes[0];

    const int blocks = 2048;   // 8 warps/block -> 16384 warps, 8 samples/warp
    bahdanau_kernel<<<blocks, 256>>>(group_inputs, item_inputs, members,
                                     user_emb, item_emb, genres,
                                     attn_W, attn_b, pred_W1, pred_b1,
                                     pred_W2, pred_b2, out, n);
}

// round 4
// speedup vs baseline: 1.8801x; 1.3714x over previous
#include <cuda_runtime.h>

// BAHDANAUplus — group recommendation scoring head. One warp per sample.
// R3: depth-2 software pipeline — embedding gathers for sample s+1 are issued
//     one full iteration before they're consumed, so gather latency overlaps
//     with compute of sample s. Index chain prefetched two iterations ahead.

#define EMB 32
#define FULLMASK 0xffffffffu

__global__ __launch_bounds__(256) void bahdanau_kernel(
    const int*   __restrict__ group_inputs,
    const int*   __restrict__ item_inputs,
    const int*   __restrict__ members,
    const float* __restrict__ user_emb,
    const float* __restrict__ item_emb,
    const float* __restrict__ genres,
    const float* __restrict__ attn_W,
    const float* __restrict__ attn_b,
    const float* __restrict__ pred_W1,
    const float* __restrict__ pred_b1,
    const float* __restrict__ pred_W2,
    const float* __restrict__ pred_b2,
    float*       __restrict__ out,
    int n)
{
    const int lane = threadIdx.x & 31;
    const int wid  = threadIdx.x >> 5;
    const int gw   = blockIdx.x * 8 + wid;
    const int nw   = gridDim.x * 8;

    // ---- hoisted per-lane weights (loop invariant, lane-indexed) ----
    float aw[4][3];
    #pragma unroll
    for (int r = 0; r < 4; r++)
        #pragma unroll
        for (int k = 0; k < 3; k++)
            aw[r][k] = attn_W[(r * 32 + lane) * 3 + k];

    float w1a[8], w1b[8], w1c[8];
    #pragma unroll
    for (int j = 0; j < 8; j++) {
        w1a[j] = pred_W1[(lane)      * 8 + j];
        w1b[j] = pred_W1[(32 + lane) * 8 + j];
        w1c[j] = pred_W1[(64 + lane) * 8 + j];
    }

    const int  ja  = (lane >> 3) & 3;
    const float abj = (ja < 3) ? attn_b[ja] : 0.0f;
    const int  jm  = (lane >> 2) & 7;
    const float b1j = pred_b1[jm];
    const float w2j = pred_W2[jm];
    const float b2  = pred_b2[0];

    const bool hi4 = (lane & 16) != 0;
    const bool hi3 = (lane & 8)  != 0;
    const bool hi2 = (lane & 4)  != 0;

    int s = gw;
    if (s >= n) return;

    // ---- prologue: fill the pipeline for sample s ----
    int grp = group_inputs[s];
    int it  = item_inputs[s];
    int m0  = members[3 * grp + 0];
    int m1  = members[3 * grp + 1];
    int m2  = members[3 * grp + 2];

    // e-values for the sample we are ABOUT to compute (sample s).
    float e0  = user_emb[m0 * EMB + lane];
    float e1  = user_emb[m1 * EMB + lane];
    float e2  = user_emb[m2 * EMB + lane];
    float itv = (lane < 14) ? item_emb[it * 14 + lane]
                            : genres[it * 18 + (lane - 14)];

    // Index chain for sample s+1.
    int s2 = s + nw;
    bool more = (s2 < n);
    int m0n = 0, m1n = 0, m2n = 0, itn = 0;
    if (more) {
        const int g2 = group_inputs[s2];
        itn = item_inputs[s2];
        m0n = members[3 * g2 + 0];
        m1n = members[3 * g2 + 1];
        m2n = members[3 * g2 + 2];
    }

    for (;;) {
        // ---- stage 1: issue gathers for sample s+1 (consumed next iter) ----
        float e0n = 0.f, e1n = 0.f, e2n = 0.f, itvn = 0.f;
        if (more) {
            e0n  = user_emb[m0n * EMB + lane];
            e1n  = user_emb[m1n * EMB + lane];
            e2n  = user_emb[m2n * EMB + lane];
            itvn = (lane < 14) ? item_emb[itn * 14 + lane]
                               : genres[itn * 18 + (lane - 14)];
        }

        // ---- stage 2: prefetch index chain for sample s+2 ----
        const int s3 = s2 + nw;
        const bool more2 = more && (s3 < n);
        int m0p = 0, m1p = 0, m2p = 0, itp = 0;
        if (more2) {
            const int g3 = group_inputs[s3];
            itp = item_inputs[s3];
            m0p = members[3 * g3 + 0];
            m1p = members[3 * g3 + 1];
            m2p = members[3 * g3 + 2];
        }

        // ---- stage 3: compute sample s (e-values loaded last iteration) ----
        float v0 = e0 * aw[0][0] + e1 * aw[1][0] + e2 * aw[2][0] + itv * aw[3][0];
        float v1 = e0 * aw[0][1] + e1 * aw[1][1] + e2 * aw[2][1] + itv * aw[3][1];
        float v2 = e0 * aw[0][2] + e1 * aw[1][2] + e2 * aw[2][2] + itv * aw[3][2];

        // Value-splitting reduce of {v0,v1,v2,0} over 32 lanes.
        float sa0 = hi4 ? v0 : v2;
        float sa1 = hi4 ? v1 : 0.0f;
        float ra0 = __shfl_xor_sync(FULLMASK, sa0, 16);
        float ra1 = __shfl_xor_sync(FULLMASK, sa1, 16);
        float u0 = (hi4 ? v2   : v0) + ra0;
        float u1 = (hi4 ? 0.0f : v1) + ra1;
        float sx = hi3 ? u0 : u1;
        float rx = __shfl_xor_sync(FULLMASK, sx, 8);
        float av = (hi3 ? u1 : u0) + rx;
        av += __shfl_xor_sync(FULLMASK, av, 4);
        av += __shfl_xor_sync(FULLMASK, av, 2);
        av += __shfl_xor_sync(FULLMASK, av, 1);
        av += abj;
        const float a0 = __shfl_sync(FULLMASK, av, 0);
        const float a1 = __shfl_sync(FULLMASK, av, 8);
        const float a2 = __shfl_sync(FULLMASK, av, 16);

        const float gv = a0 * e0 + a1 * e1 + a2 * e2;
        const float n0 = gv * itv;

        float h[8];
        #pragma unroll
        for (int j = 0; j < 8; j++)
            h[j] = n0 * w1a[j] + gv * w1b[j] + itv * w1c[j];

        // Value-splitting reduce of 8 values over 32 lanes.
        float t[4];
        #pragma unroll
        for (int k = 0; k < 4; k++) {
            float snd = hi4 ? h[k] : h[k + 4];
            float rcv = __shfl_xor_sync(FULLMASK, snd, 16);
            t[k] = (hi4 ? h[k + 4] : h[k]) + rcv;
        }
        float u[2];
        #pragma unroll
        for (int k = 0; k < 2; k++) {
            float snd = hi3 ? t[k] : t[k + 2];
            float rcv = __shfl_xor_sync(FULLMASK, snd, 8);
            u[k] = (hi3 ? t[k + 2] : t[k]) + rcv;
        }
        {
            float snd = hi2 ? u[0] : u[1];
            float rcv = __shfl_xor_sync(FULLMASK, snd, 4);
            u[0] = (hi2 ? u[1] : u[0]) + rcv;
        }
        float hh = u[0];
        hh += __shfl_xor_sync(FULLMASK, hh, 2);
        hh += __shfl_xor_sync(FULLMASK, hh, 1);

        float p = fmaxf(hh + b1j, 0.0f) * w2j;
        p += __shfl_xor_sync(FULLMASK, p, 4);
        p += __shfl_xor_sync(FULLMASK, p, 8);
        p += __shfl_xor_sync(FULLMASK, p, 16);

        const float y = 1.0f / (1.0f + __expf(-(p + b2)));
        if (lane == 0) out[s] = y;

        if (!more) break;

        // ---- rotate pipeline state ----
        s   = s2;  s2 = s3;  more = more2;
        e0  = e0n; e1 = e1n; e2 = e2n; itv = itvn;
        m0n = m0p; m1n = m1p; m2n = m2p; itn = itp;
    }
}

extern "C" void kernel_launch(void* const* d_in, const int* in_sizes, int n_in,
                              void* d_out, int out_size)
{
    (void)n_in; (void)out_size;
    const int*   group_inputs = (const int*)  d_in[0];
    const int*   item_inputs  = (const int*)  d_in[1];
    const int*   members      = (const int*)  d_in[2];
    const float* user_emb     = (const float*)d_in[3];
    const float* item_emb     = (const float*)d_in[4];
    const float* genres       = (const float*)d_in[5];
    const float* attn_W       = (const float*)d_in[6];
    const float* attn_b       = (const float*)d_in[7];
    const float* pred_W1      = (const float*)d_in[8];
    const float* pred_b1      = (const float*)d_in[9];
    const float* pred_W2      = (const float*)d_in[10];
    const float* pred_b2      = (const float*)d_in[11];
    float* out = (float*)d_out;
    const int n = in_sizes[0];

    const int blocks = 2048;   // 8 warps/block -> 16384 warps, 8 samples/warp
    bahdanau_kernel<<<blocks, 256>>>(group_inputs, item_inputs, members,
                                     user_emb, item_emb, genres,
                                     attn_W, attn_b, pred_W1, pred_b1,
                                     pred_W2, pred_b2, out, n);
}

// round 6
// speedup vs baseline: 1.9610x; 1.0430x over previous
#include <cuda_runtime.h>

// BAHDANAUplus — group recommendation scoring head. One warp per sample-PAIR.
// R6: two independent samples interleaved per warp (straight-line unroll) so
//     their shuffle dependency chains overlap; attn reduce = 3 parallel plain
//     butterflies (depth 5, no broadcasts); MLP reduce = value-splitting
//     (9 shfl) + 3-shfl orbit sum. Depth-2 load pipeline per slot retained.

#define EMB 32
#define FULLMASK 0xffffffffu

__global__ __launch_bounds__(256) void bahdanau_kernel(
    const int*   __restrict__ group_inputs,
    const int*   __restrict__ item_inputs,
    const int*   __restrict__ members,
    const float* __restrict__ user_emb,
    const float* __restrict__ item_emb,
    const float* __restrict__ genres,
    const float* __restrict__ attn_W,
    const float* __restrict__ attn_b,
    const float* __restrict__ pred_W1,
    const float* __restrict__ pred_b1,
    const float* __restrict__ pred_W2,
    const float* __restrict__ pred_b2,
    float*       __restrict__ out,
    int n)
{
    const int lane = threadIdx.x & 31;
    const int wid  = threadIdx.x >> 5;
    const int gw   = blockIdx.x * 8 + wid;
    const int nw   = gridDim.x * 8;
    const int stride = nw * 2;         // two samples per warp per iteration

    // ---- hoisted per-lane weights (loop invariant, lane-indexed) ----
    float aw[4][3];
    #pragma unroll
    for (int r = 0; r < 4; r++)
        #pragma unroll
        for (int k = 0; k < 3; k++)
            aw[r][k] = attn_W[(r * 32 + lane) * 3 + k];

    float w1a[8], w1b[8], w1c[8];
    #pragma unroll
    for (int j = 0; j < 8; j++) {
        w1a[j] = pred_W1[(lane)      * 8 + j];
        w1b[j] = pred_W1[(32 + lane) * 8 + j];
        w1c[j] = pred_W1[(64 + lane) * 8 + j];
    }

    const float ab0 = attn_b[0], ab1 = attn_b[1], ab2 = attn_b[2];
    const int  jm  = (lane >> 2) & 7;      // MLP hidden unit owned after split
    const float b1j = pred_b1[jm];
    const float w2j = pred_W2[jm];
    const float b2  = pred_b2[0];

    const bool hi4 = (lane & 16) != 0;
    const bool hi3 = (lane & 8)  != 0;
    const bool hi2 = (lane & 4)  != 0;

    int base = gw * 2;
    if (base >= n) return;

    // ---- pipeline state: 2 slots ----
    int   sc[2]; bool vc[2];          // current sample id / valid
    float ec[2][4];                   // current e0,e1,e2,itv
    int   sn[2]; bool vn[2];          // next sample id / valid
    int   mn[2][4];                   // next indices m0,m1,m2,it

    #pragma unroll
    for (int t = 0; t < 2; t++) {
        sc[t] = base + t;
        vc[t] = (sc[t] < n);
        const int sl = vc[t] ? sc[t] : 0;
        const int g  = group_inputs[sl];
        const int it = item_inputs[sl];
        const int m0 = members[3 * g + 0];
        const int m1 = members[3 * g + 1];
        const int m2 = members[3 * g + 2];
        ec[t][0] = user_emb[m0 * EMB + lane];
        ec[t][1] = user_emb[m1 * EMB + lane];
        ec[t][2] = user_emb[m2 * EMB + lane];
        ec[t][3] = (lane < 14) ? item_emb[it * 14 + lane]
                               : genres[it * 18 + (lane - 14)];

        sn[t] = sc[t] + stride;
        vn[t] = (sn[t] < n);
        const int sl2 = vn[t] ? sn[t] : 0;
        const int g2  = group_inputs[sl2];
        mn[t][3] = item_inputs[sl2];
        mn[t][0] = members[3 * g2 + 0];
        mn[t][1] = members[3 * g2 + 1];
        mn[t][2] = members[3 * g2 + 2];
    }

    for (;;) {
        // ---- stage 1: issue gathers for the next pair ----
        float en[2][4];
        #pragma unroll
        for (int t = 0; t < 2; t++) {
            en[t][0] = user_emb[mn[t][0] * EMB + lane];
            en[t][1] = user_emb[mn[t][1] * EMB + lane];
            en[t][2] = user_emb[mn[t][2] * EMB + lane];
            en[t][3] = (lane < 14) ? item_emb[mn[t][3] * 14 + lane]
                                   : genres[mn[t][3] * 18 + (lane - 14)];
        }

        // ---- stage 2: prefetch index chain for the pair after that ----
        int sq[2]; bool vq[2]; int mq[2][4];
        #pragma unroll
        for (int t = 0; t < 2; t++) {
            sq[t] = sn[t] + stride;
            vq[t] = (sq[t] < n);
            const int sl = vq[t] ? sq[t] : 0;
            const int g  = group_inputs[sl];
            mq[t][3] = item_inputs[sl];
            mq[t][0] = members[3 * g + 0];
            mq[t][1] = members[3 * g + 1];
            mq[t][2] = members[3 * g + 2];
        }

        // ---- stage 3: compute both current samples (interleaved chains) ----
        #pragma unroll
        for (int t = 0; t < 2; t++) {
            const float e0  = ec[t][0];
            const float e1  = ec[t][1];
            const float e2  = ec[t][2];
            const float itv = ec[t][3];

            // Attention logits: 3 parallel plain butterflies (all-lanes result).
            float v0 = e0 * aw[0][0] + e1 * aw[1][0] + e2 * aw[2][0] + itv * aw[3][0];
            float v1 = e0 * aw[0][1] + e1 * aw[1][1] + e2 * aw[2][1] + itv * aw[3][1];
            float v2 = e0 * aw[0][2] + e1 * aw[1][2] + e2 * aw[2][2] + itv * aw[3][2];
            #pragma unroll
            for (int off = 16; off > 0; off >>= 1) {
                v0 += __shfl_xor_sync(FULLMASK, v0, off);
                v1 += __shfl_xor_sync(FULLMASK, v1, off);
                v2 += __shfl_xor_sync(FULLMASK, v2, off);
            }
            const float a0 = v0 + ab0;
            const float a1 = v1 + ab1;
            const float a2 = v2 + ab2;

            const float gv = a0 * e0 + a1 * e1 + a2 * e2;
            const float n0 = gv * itv;

            float h[8];
            #pragma unroll
            for (int j = 0; j < 8; j++)
                h[j] = n0 * w1a[j] + gv * w1b[j] + itv * w1c[j];

            // Value-splitting reduce of 8 values over 32 lanes (9 shfl, depth 5).
            float tt[4];
            #pragma unroll
            for (int k = 0; k < 4; k++) {
                float snd = hi4 ? h[k] : h[k + 4];
                float rcv = __shfl_xor_sync(FULLMASK, snd, 16);
                tt[k] = (hi4 ? h[k + 4] : h[k]) + rcv;
            }
            float uu[2];
            #pragma unroll
            for (int k = 0; k < 2; k++) {
                float snd = hi3 ? tt[k] : tt[k + 2];
                float rcv = __shfl_xor_sync(FULLMASK, snd, 8);
                uu[k] = (hi3 ? tt[k + 2] : tt[k]) + rcv;
            }
            float snd = hi2 ? uu[0] : uu[1];
            float rcv = __shfl_xor_sync(FULLMASK, snd, 4);
            float hh = (hi2 ? uu[1] : uu[0]) + rcv;
            hh += __shfl_xor_sync(FULLMASK, hh, 2);
            hh += __shfl_xor_sync(FULLMASK, hh, 1);
            // hh = complete h_jm, jm = (lane>>2)&7.

            float p = fmaxf(hh + b1j, 0.0f) * w2j;
            p += __shfl_xor_sync(FULLMASK, p, 4);
            p += __shfl_xor_sync(FULLMASK, p, 8);
            p += __shfl_xor_sync(FULLMASK, p, 16);

            const float y = __fdividef(1.0f, 1.0f + __expf(-(p + b2)));
            if (lane == 0 && vc[t]) out[sc[t]] = y;
        }

        if (!vn[0] && !vn[1]) break;

        // ---- rotate pipeline state ----
        #pragma unroll
        for (int t = 0; t < 2; t++) {
            sc[t] = sn[t]; vc[t] = vn[t];
            ec[t][0] = en[t][0]; ec[t][1] = en[t][1];
            ec[t][2] = en[t][2]; ec[t][3] = en[t][3];
            sn[t] = sq[t]; vn[t] = vq[t];
            mn[t][0] = mq[t][0]; mn[t][1] = mq[t][1];
            mn[t][2] = mq[t][2]; mn[t][3] = mq[t][3];
        }
    }
}

extern "C" void kernel_launch(void* const* d_in, const int* in_sizes, int n_in,
                              void* d_out, int out_size)
{
    (void)n_in; (void)out_size;
    const int*   group_inputs = (const int*)  d_in[0];
    const int*   item_inputs  = (const int*)  d_in[1];
    const int*   members      = (const int*)  d_in[2];
    const float* user_emb     = (const float*)d_in[3];
    const float* item_emb     = (const float*)d_in[4];
    const float* genres       = (const float*)d_in[5];
    const float* attn_W       = (const float*)d_in[6];
    const float* attn_b       = (const float*)d_in[7];
    const float* pred_W1      = (const float*)d_in[8];
    const float* pred_b1      = (const float*)d_in[9];
    const float* pred_W2      = (const float*)d_in[10];
    const float* pred_b2      = (const float*)d_in[11];
    float* out = (float*)d_out;
    const int n = in_sizes[0];

    // 2048 blocks x 8 warps x 2 samples = 32768 slots -> 4 iterations each.
    const int blocks = 2048;
    bahdanau_kernel<<<blocks, 256>>>(group_inputs, item_inputs, members,
                                     user_emb, item_emb, genres,
                                     attn_W, attn_b, pred_W1, pred_b1,
                                     pred_W2, pred_b2, out, n);
}

// round 7
// speedup vs baseline: 2.8092x; 1.4326x over previous
#include <cuda_runtime.h>

// BAHDANAUplus — R7: 16 lanes per sample, 2 samples per warp (lane bit 4),
// 2 dims per lane (float2). Warp reductions run over 16 lanes and one shfl
// instruction serves BOTH samples: ~11.5 shfl/sample vs 27. Depth-2 load
// pipeline retained. Vectorized weight preload, 128-thread blocks.

#define FULLMASK 0xffffffffu

__global__ __launch_bounds__(128) void bahdanau_kernel(
    const int*   __restrict__ group_inputs,
    const int*   __restrict__ item_inputs,
    const int*   __restrict__ members,
    const float* __restrict__ user_emb,
    const float* __restrict__ item_emb,
    const float* __restrict__ genres,
    const float* __restrict__ attn_W,
    const float* __restrict__ attn_b,
    const float* __restrict__ pred_W1,
    const float* __restrict__ pred_b1,
    const float* __restrict__ pred_W2,
    const float* __restrict__ pred_b2,
    float*       __restrict__ out,
    int n)
{
    const int lane = threadIdx.x & 31;
    const int sub  = lane & 15;          // position within the sample's 16-lane group
    const int half = lane >> 4;          // which sample of the pair
    const int wid  = threadIdx.x >> 5;
    const int gw   = blockIdx.x * 4 + wid;
    const int nwarp = gridDim.x * 4;
    const int stride = nwarp * 2;        // samples consumed per iteration

    const int d0 = sub * 2;              // this lane's first dim

    // ---- attn_W: rows {d0, d0+1} of each 32-row segment; 6 consecutive
    //      floats starting at (seg*32+d0)*3 (24B-aligned -> 3x float2). ----
    float aw[2][4][3];                   // [dim][segment][k]
    #pragma unroll
    for (int seg = 0; seg < 4; seg++) {
        const float2* p = (const float2*)(attn_W + (seg * 32 + d0) * 3);
        const float2 q0 = p[0], q1 = p[1], q2 = p[2];
        aw[0][seg][0] = q0.x; aw[0][seg][1] = q0.y; aw[0][seg][2] = q1.x;
        aw[1][seg][0] = q1.y; aw[1][seg][1] = q2.x; aw[1][seg][2] = q2.y;
    }

    // ---- pred_W1: rows {r*32 + d0 + dl}, 8 floats each (32B, float4 x2) ----
    float w1[2][3][8];                   // [dim][row-segment][j]
    #pragma unroll
    for (int dl = 0; dl < 2; dl++)
        #pragma unroll
        for (int r = 0; r < 3; r++) {
            const float4* p = (const float4*)(pred_W1 + (r * 32 + d0 + dl) * 8);
            const float4 a = p[0], b = p[1];
            w1[dl][r][0] = a.x; w1[dl][r][1] = a.y; w1[dl][r][2] = a.z; w1[dl][r][3] = a.w;
            w1[dl][r][4] = b.x; w1[dl][r][5] = b.y; w1[dl][r][6] = b.z; w1[dl][r][7] = b.w;
        }

    const float ab0 = attn_b[0], ab1 = attn_b[1], ab2 = attn_b[2];
    const int   jm  = (lane >> 1) & 7;   // hidden unit owned after value-split
    const float b1j = pred_b1[jm];
    const float w2j = pred_W2[jm];
    const float b2  = pred_b2[0];

    const bool q3 = (lane & 8) != 0;
    const bool q2b = (lane & 4) != 0;
    const bool q1b = (lane & 2) != 0;

    const float2* ue = (const float2*)user_emb;   // 16 float2 per row
    const float2* ie = (const float2*)item_emb;   // 7 float2 per row
    const float2* ge = (const float2*)genres;     // 9 float2 per row

    int bc = gw * 2;                     // current base; my sample = bc + half
    if (bc >= n) return;

    // ---- prologue: sample for this iteration ----
    int  scur = bc + half;
    bool vC   = (scur < n);
    {
        // indices + embeddings for current sample
    }
    int scl = vC ? scur : 0;
    int g   = group_inputs[scl];
    int it  = item_inputs[scl];
    int m0  = members[3 * g + 0];
    int m1  = members[3 * g + 1];
    int m2  = members[3 * g + 2];
    float2 e0  = ue[m0 * 16 + sub];
    float2 e1  = ue[m1 * 16 + sub];
    float2 e2  = ue[m2 * 16 + sub];
    float2 itv = (sub < 7) ? ie[it * 7 + sub] : ge[it * 9 + (sub - 7)];

    // indices for next iteration's sample
    int  bn   = bc + stride;
    int  snx  = bn + half;
    bool vN   = (snx < n);
    int  snl  = vN ? snx : 0;
    int  gn   = group_inputs[snl];
    int  itn  = item_inputs[snl];
    int  m0n  = members[3 * gn + 0];
    int  m1n  = members[3 * gn + 1];
    int  m2n  = members[3 * gn + 2];

    for (;;) {
        // ---- stage 1: issue gathers for next iteration ----
        const float2 e0n  = ue[m0n * 16 + sub];
        const float2 e1n  = ue[m1n * 16 + sub];
        const float2 e2n  = ue[m2n * 16 + sub];
        const float2 itvn = (sub < 7) ? ie[itn * 7 + sub] : ge[itn * 9 + (sub - 7)];

        // ---- stage 2: prefetch index chain for iteration after next ----
        const int  bq  = bn + stride;
        const int  sqx = bq + half;
        const bool vQ  = (sqx < n);
        const int  sql = vQ ? sqx : 0;
        const int  gq  = group_inputs[sql];
        const int  itq = item_inputs[sql];
        const int  m0q = members[3 * gq + 0];
        const int  m1q = members[3 * gq + 1];
        const int  m2q = members[3 * gq + 2];

        // ---- stage 3: compute current sample (per 16-lane group) ----
        float v0 = e0.x * aw[0][0][0] + e0.y * aw[1][0][0]
                 + e1.x * aw[0][1][0] + e1.y * aw[1][1][0]
                 + e2.x * aw[0][2][0] + e2.y * aw[1][2][0]
                 + itv.x * aw[0][3][0] + itv.y * aw[1][3][0];
        float v1 = e0.x * aw[0][0][1] + e0.y * aw[1][0][1]
                 + e1.x * aw[0][1][1] + e1.y * aw[1][1][1]
                 + e2.x * aw[0][2][1] + e2.y * aw[1][2][1]
                 + itv.x * aw[0][3][1] + itv.y * aw[1][3][1];
        float v2 = e0.x * aw[0][0][2] + e0.y * aw[1][0][2]
                 + e1.x * aw[0][1][2] + e1.y * aw[1][1][2]
                 + e2.x * aw[0][2][2] + e2.y * aw[1][2][2]
                 + itv.x * aw[0][3][2] + itv.y * aw[1][3][2];

        // Butterfly over the 16-lane group (both samples share instructions).
        #pragma unroll
        for (int off = 8; off > 0; off >>= 1) {
            v0 += __shfl_xor_sync(FULLMASK, v0, off);
            v1 += __shfl_xor_sync(FULLMASK, v1, off);
            v2 += __shfl_xor_sync(FULLMASK, v2, off);
        }
        const float a0 = v0 + ab0;
        const float a1 = v1 + ab1;
        const float a2 = v2 + ab2;

        float2 gv, n0;
        gv.x = a0 * e0.x + a1 * e1.x + a2 * e2.x;
        gv.y = a0 * e0.y + a1 * e1.y + a2 * e2.y;
        n0.x = gv.x * itv.x;
        n0.y = gv.y * itv.y;

        float h[8];
        #pragma unroll
        for (int j = 0; j < 8; j++)
            h[j] = n0.x * w1[0][0][j] + n0.y * w1[1][0][j]
                 + gv.x * w1[0][1][j] + gv.y * w1[1][1][j]
                 + itv.x * w1[0][2][j] + itv.y * w1[1][2][j];

        // Value-splitting reduce of 8 values over the 16-lane group.
        float t[4];
        #pragma unroll
        for (int k = 0; k < 4; k++) {               // off=8: 8 -> 4
            const float snd = q3 ? h[k] : h[k + 4];
            const float rcv = __shfl_xor_sync(FULLMASK, snd, 8);
            t[k] = (q3 ? h[k + 4] : h[k]) + rcv;
        }
        float u[2];
        #pragma unroll
        for (int k = 0; k < 2; k++) {               // off=4: 4 -> 2
            const float snd = q2b ? t[k] : t[k + 2];
            const float rcv = __shfl_xor_sync(FULLMASK, snd, 4);
            u[k] = (q2b ? t[k + 2] : t[k]) + rcv;
        }
        {
            const float snd = q1b ? u[0] : u[1];    // off=2: 2 -> 1
            const float rcv = __shfl_xor_sync(FULLMASK, snd, 2);
            u[0] = (q1b ? u[1] : u[0]) + rcv;
        }
        float hh = u[0] + __shfl_xor_sync(FULLMASK, u[0], 1);
        // hh = complete h_jm, jm = (lane>>1)&7 within this sample's group.

        float p = fmaxf(hh + b1j, 0.0f) * w2j;
        p += __shfl_xor_sync(FULLMASK, p, 2);       // orbit over lane bits 1..3
        p += __shfl_xor_sync(FULLMASK, p, 4);
        p += __shfl_xor_sync(FULLMASK, p, 8);

        const float y = __fdividef(1.0f, 1.0f + __expf(-(p + b2)));
        if (sub == 0 && vC) out[scur] = y;

        if (bn >= n) break;                          // no next sample anywhere

        // ---- rotate pipeline state ----
        bc = bn; scur = snx; vC = vN;
        e0 = e0n; e1 = e1n; e2 = e2n; itv = itvn;
        bn = bq; snx = sqx; vN = vQ;
        m0n = m0q; m1n = m1q; m2n = m2q; itn = itq;
    }
}

extern "C" void kernel_launch(void* const* d_in, const int* in_sizes, int n_in,
                              void* d_out, int out_size)
{
    (void)n_in; (void)out_size;
    const int*   group_inputs = (const int*)  d_in[0];
    const int*   item_inputs  = (const int*)  d_in[1];
    const int*   members      = (const int*)  d_in[2];
    const float* user_emb     = (const float*)d_in[3];
    const float* item_emb     = (const float*)d_in[4];
    const float* genres       = (const float*)d_in[5];
    const float* attn_W       = (const float*)d_in[6];
    const float* attn_b       = (const float*)d_in[7];
    const float* pred_W1      = (const float*)d_in[8];
    const float* pred_b1      = (const float*)d_in[9];
    const float* pred_W2      = (const float*)d_in[10];
    const float* pred_b2      = (const float*)d_in[11];
    float* out = (float*)d_out;
    const int n = in_sizes[0];

    // 2048 blocks x 4 warps x 2 samples = 16384 slots -> 8 iterations each
    // (amortizes the per-thread weight preload and pipeline prologue).
    const int blocks = 2048;
    bahdanau_kernel<<<blocks, 128>>>(group_inputs, item_inputs, members,
                                     user_emb, item_emb, genres,
                                     attn_W, attn_b, pred_W1, pred_b1,
                                     pred_W2, pred_b2, out, n);
}